// round 1
// baseline (speedup 1.0000x reference)
#include <cuda_runtime.h>

#define SEQ  2048
#define DM   1024
#define NH   16
#define HD   64
#define NB   2
#define MROWS (NB*SEQ)

// Scratch (device globals — no allocation allowed)
__device__ float g_q[(size_t)NB*NH*SEQ*HD];
__device__ float g_k[(size_t)NB*NH*SEQ*HD];
__device__ float g_v[(size_t)NB*NH*SEQ*HD];
__device__ float g_attn[(size_t)NB*SEQ*DM];

// ---------------------------------------------------------------------------
// GEMM: C[M,N] = A[M,K] @ W[N,K]^T + bias[N]
// MODE 0: scatter epilogue into g_q/g_k/g_v with [B,H,N,hd] layout
// MODE 1: plain row-major store into C
// BM=BN=128, BK=16, 256 threads, 8x8 micro-tile, register prefetch.
// ---------------------------------------------------------------------------
template<int MODE>
__global__ void __launch_bounds__(256)
gemm_nt(const float* __restrict__ A, const float* __restrict__ W,
        const float* __restrict__ bias, float* __restrict__ C,
        int M, int N, int K)
{
    __shared__ float As[16][128];
    __shared__ float Bs[16][128];

    const int tid = threadIdx.x;
    const int tx = tid & 15, ty = tid >> 4;
    const int bm = blockIdx.y * 128, bn = blockIdx.x * 128;

    // Global load mapping: each thread loads 2 float4 from A and 2 from W.
    const int lrow = tid >> 2;          // 0..63
    const int lc   = (tid & 3) * 4;     // 0,4,8,12
    const float* Ag = A + (size_t)(bm + lrow) * K + lc;
    const float* Wg = W + (size_t)(bn + lrow) * K + lc;
    const size_t strR = (size_t)64 * K;

    float4 a0 = *(const float4*)(Ag);
    float4 a1 = *(const float4*)(Ag + strR);
    float4 b0 = *(const float4*)(Wg);
    float4 b1 = *(const float4*)(Wg + strR);

    float acc[8][8];
#pragma unroll
    for (int i = 0; i < 8; i++)
#pragma unroll
        for (int j = 0; j < 8; j++) acc[i][j] = 0.f;

    const int nk = K / 16;
    for (int kt = 0; kt < nk; kt++) {
        // regs -> smem (transposed: As[k][m])
        As[lc+0][lrow]    = a0.x; As[lc+1][lrow]    = a0.y;
        As[lc+2][lrow]    = a0.z; As[lc+3][lrow]    = a0.w;
        As[lc+0][lrow+64] = a1.x; As[lc+1][lrow+64] = a1.y;
        As[lc+2][lrow+64] = a1.z; As[lc+3][lrow+64] = a1.w;
        Bs[lc+0][lrow]    = b0.x; Bs[lc+1][lrow]    = b0.y;
        Bs[lc+2][lrow]    = b0.z; Bs[lc+3][lrow]    = b0.w;
        Bs[lc+0][lrow+64] = b1.x; Bs[lc+1][lrow+64] = b1.y;
        Bs[lc+2][lrow+64] = b1.z; Bs[lc+3][lrow+64] = b1.w;
        __syncthreads();

        if (kt + 1 < nk) {  // prefetch next tile (latency hidden under compute)
            const float* Ag2 = Ag + (size_t)(kt + 1) * 16;
            const float* Wg2 = Wg + (size_t)(kt + 1) * 16;
            a0 = *(const float4*)(Ag2);
            a1 = *(const float4*)(Ag2 + strR);
            b0 = *(const float4*)(Wg2);
            b1 = *(const float4*)(Wg2 + strR);
        }

#pragma unroll
        for (int k = 0; k < 16; k++) {
            float4 af0 = *(const float4*)&As[k][ty * 8];
            float4 af1 = *(const float4*)&As[k][ty * 8 + 4];
            float4 bf0 = *(const float4*)&Bs[k][tx * 8];
            float4 bf1 = *(const float4*)&Bs[k][tx * 8 + 4];
            float av[8] = {af0.x, af0.y, af0.z, af0.w, af1.x, af1.y, af1.z, af1.w};
            float bv[8] = {bf0.x, bf0.y, bf0.z, bf0.w, bf1.x, bf1.y, bf1.z, bf1.w};
#pragma unroll
            for (int i = 0; i < 8; i++)
#pragma unroll
                for (int j = 0; j < 8; j++)
                    acc[i][j] = fmaf(av[i], bv[j], acc[i][j]);
        }
        __syncthreads();
    }

    const int row0 = bm + ty * 8, col0 = bn + tx * 8;
#pragma unroll
    for (int i = 0; i < 8; i++) {
        const int m = row0 + i;
#pragma unroll
        for (int j = 0; j < 8; j++) {
            const int n = col0 + j;
            const float v = acc[i][j] + __ldg(&bias[n]);
            if (MODE == 0) {
                const int chunk = n >> 10;          // 0=q 1=k 2=v
                const int rem = n & 1023;
                const int h = rem >> 6, d = rem & 63;
                const int b = m >> 11, t = m & 2047;
                float* dst = (chunk == 0) ? g_q : (chunk == 1) ? g_k : g_v;
                dst[(((size_t)b * NH + h) * SEQ + t) * HD + d] = v;
            } else {
                C[(size_t)m * N + n] = v;
            }
        }
    }
}

// ---------------------------------------------------------------------------
// Flash attention fp32.
// Block = (128 queries) x (one b,h). 256 threads: trow=tid/8 owns 4 q-rows,
// tcol=tid%8 owns 8 cols. K-tile = 64 keys. Online softmax, width-8 shuffles.
// ---------------------------------------------------------------------------
__global__ void __launch_bounds__(256) attn_kernel()
{
    extern __shared__ float sm[];
    float* Qs = sm;                  // 128 x 65
    float* Ks = Qs + 128 * 65;       //  64 x 65
    float* Vs = Ks + 64 * 65;        //  64 x 65
    float* Ps = Vs + 64 * 65;        // 128 x 65

    const int tid = threadIdx.x;
    const int tcol = tid & 7, trow = tid >> 3;
    const int r0 = trow * 4, c0 = tcol * 8;
    const int bh = blockIdx.y;
    const int q0 = blockIdx.x * 128;

    const float* Qg = g_q + (size_t)bh * SEQ * HD;
    const float* Kg = g_k + (size_t)bh * SEQ * HD;
    const float* Vg = g_v + (size_t)bh * SEQ * HD;

    const float scale = 0.125f;  // HD^-0.5, folded into Q at load

#pragma unroll
    for (int it = 0; it < 8; it++) {
        const int v = tid + 256 * it;               // 2048 float4
        const int row = v >> 4, c = (v & 15) * 4;
        float4 q4 = *(const float4*)(Qg + (size_t)(q0 + row) * HD + c);
        Qs[row * 65 + c + 0] = q4.x * scale;
        Qs[row * 65 + c + 1] = q4.y * scale;
        Qs[row * 65 + c + 2] = q4.z * scale;
        Qs[row * 65 + c + 3] = q4.w * scale;
    }

    float m_i[4], l_i[4], Of[4][8];
#pragma unroll
    for (int i = 0; i < 4; i++) {
        m_i[i] = -1e30f; l_i[i] = 0.f;
#pragma unroll
        for (int j = 0; j < 8; j++) Of[i][j] = 0.f;
    }

    for (int kt = 0; kt < SEQ / 64; kt++) {
        __syncthreads();  // prev PV done (and Q visible on kt=0) before K/V overwrite
#pragma unroll
        for (int it = 0; it < 4; it++) {
            const int v = tid + 256 * it;           // 1024 float4 per tile
            const int row = v >> 4, c = (v & 15) * 4;
            float4 k4 = *(const float4*)(Kg + (size_t)(kt * 64 + row) * HD + c);
            float4 v4 = *(const float4*)(Vg + (size_t)(kt * 64 + row) * HD + c);
            Ks[row * 65 + c + 0] = k4.x; Ks[row * 65 + c + 1] = k4.y;
            Ks[row * 65 + c + 2] = k4.z; Ks[row * 65 + c + 3] = k4.w;
            Vs[row * 65 + c + 0] = v4.x; Vs[row * 65 + c + 1] = v4.y;
            Vs[row * 65 + c + 2] = v4.z; Vs[row * 65 + c + 3] = v4.w;
        }
        __syncthreads();

        // S = Q K^T  (4x8 fragment)
        float s[4][8];
#pragma unroll
        for (int i = 0; i < 4; i++)
#pragma unroll
            for (int j = 0; j < 8; j++) s[i][j] = 0.f;

#pragma unroll 8
        for (int k = 0; k < 64; k++) {
            float av[4], bv[8];
#pragma unroll
            for (int i = 0; i < 4; i++) av[i] = Qs[(r0 + i) * 65 + k];
#pragma unroll
            for (int j = 0; j < 8; j++) bv[j] = Ks[(c0 + j) * 65 + k];
#pragma unroll
            for (int i = 0; i < 4; i++)
#pragma unroll
                for (int j = 0; j < 8; j++)
                    s[i][j] = fmaf(av[i], bv[j], s[i][j]);
        }

        // online softmax (row groups of 8 lanes)
#pragma unroll
        for (int i = 0; i < 4; i++) {
            float mx = s[i][0];
#pragma unroll
            for (int j = 1; j < 8; j++) mx = fmaxf(mx, s[i][j]);
            mx = fmaxf(mx, __shfl_xor_sync(0xffffffffu, mx, 4, 8));
            mx = fmaxf(mx, __shfl_xor_sync(0xffffffffu, mx, 2, 8));
            mx = fmaxf(mx, __shfl_xor_sync(0xffffffffu, mx, 1, 8));
            const float mnew = fmaxf(m_i[i], mx);
            const float alpha = __expf(m_i[i] - mnew);
            float rs = 0.f;
#pragma unroll
            for (int j = 0; j < 8; j++) {
                const float p = __expf(s[i][j] - mnew);
                s[i][j] = p; rs += p;
            }
            rs += __shfl_xor_sync(0xffffffffu, rs, 4, 8);
            rs += __shfl_xor_sync(0xffffffffu, rs, 2, 8);
            rs += __shfl_xor_sync(0xffffffffu, rs, 1, 8);
            l_i[i] = l_i[i] * alpha + rs;
            m_i[i] = mnew;
#pragma unroll
            for (int j = 0; j < 8; j++) Of[i][j] *= alpha;
#pragma unroll
            for (int j = 0; j < 8; j++) Ps[(r0 + i) * 65 + c0 + j] = s[i][j];
        }
        __syncthreads();

        // O += P V
#pragma unroll 8
        for (int k = 0; k < 64; k++) {
            float pv[4], vv[8];
#pragma unroll
            for (int i = 0; i < 4; i++) pv[i] = Ps[(r0 + i) * 65 + k];
#pragma unroll
            for (int j = 0; j < 8; j++) vv[j] = Vs[k * 65 + c0 + j];
#pragma unroll
            for (int i = 0; i < 4; i++)
#pragma unroll
                for (int j = 0; j < 8; j++)
                    Of[i][j] = fmaf(pv[i], vv[j], Of[i][j]);
        }
    }

    // epilogue -> g_attn in [B, N, H*hd] layout (proj GEMM A operand)
    const int b = bh >> 4, h = bh & 15;
#pragma unroll
    for (int i = 0; i < 4; i++) {
        const float inv = 1.f / l_i[i];
        const int q = q0 + r0 + i;
#pragma unroll
        for (int j = 0; j < 8; j++)
            g_attn[((size_t)b * SEQ + q) * DM + h * HD + c0 + j] = Of[i][j] * inv;
    }
}

// ---------------------------------------------------------------------------
extern "C" void kernel_launch(void* const* d_in, const int* in_sizes, int n_in,
                              void* d_out, int out_size)
{
    const float* x      = (const float*)d_in[0];
    const float* qkv_w  = (const float*)d_in[1];
    const float* qkv_b  = (const float*)d_in[2];
    const float* proj_w = (const float*)d_in[3];
    const float* proj_b = (const float*)d_in[4];
    float* out = (float*)d_out;

    void* attn_ptr = nullptr;
    cudaGetSymbolAddress(&attn_ptr, g_attn);

    const size_t smem = (size_t)(128 + 64 + 64 + 128) * 65 * sizeof(float);  // 99840
    cudaFuncSetAttribute(attn_kernel, cudaFuncAttributeMaxDynamicSharedMemorySize,
                         (int)smem);

    dim3 blk(256);
    // 1) QKV = x @ qkv_w^T + qkv_b, scattered to [B,H,N,hd]
    gemm_nt<0><<<dim3(3 * DM / 128, MROWS / 128), blk>>>(
        x, qkv_w, qkv_b, nullptr, MROWS, 3 * DM, DM);
    // 2) attention
    attn_kernel<<<dim3(SEQ / 128, NB * NH), blk, smem>>>();
    // 3) out = attn @ proj_w^T + proj_b
    gemm_nt<1><<<dim3(DM / 128, MROWS / 128), blk>>>(
        (const float*)attn_ptr, proj_w, proj_b, out, MROWS, DM, DM);
}

// round 2
// speedup vs baseline: 1.0169x; 1.0169x over previous
#include <cuda_runtime.h>

#define SEQ  2048
#define DM   1024
#define NH   16
#define HD   64
#define NB   2
#define MROWS (NB*SEQ)

// Scratch (device globals — no allocation allowed)
__device__ float g_q[(size_t)NB*NH*SEQ*HD];
__device__ float g_k[(size_t)NB*NH*SEQ*HD];
__device__ float g_v[(size_t)NB*NH*SEQ*HD];
__device__ float g_attn[(size_t)NB*SEQ*DM];

// ---- packed f32x2 helpers (sm_103a dual-fp32 pipe) -------------------------
typedef unsigned long long u64;

__device__ __forceinline__ u64 pk2(float a, float b) {
    u64 r; asm("mov.b64 %0,{%1,%2};" : "=l"(r) : "f"(a), "f"(b)); return r;
}
__device__ __forceinline__ u64 dup2(float a) {
    u64 r; asm("mov.b64 %0,{%1,%1};" : "=l"(r) : "f"(a)); return r;
}
__device__ __forceinline__ void fma2(u64& d, u64 a, u64 b) {
    asm("fma.rn.f32x2 %0,%1,%2,%0;" : "+l"(d) : "l"(a), "l"(b));
}
__device__ __forceinline__ u64 mul2(u64 a, u64 b) {
    u64 r; asm("mul.rn.f32x2 %0,%1,%2;" : "=l"(r) : "l"(a), "l"(b)); return r;
}
__device__ __forceinline__ float2 up2(u64 v) {
    float2 f; asm("mov.b64 {%0,%1},%2;" : "=f"(f.x), "=f"(f.y) : "l"(v)); return f;
}

// ---------------------------------------------------------------------------
// GEMM: C[M,N] = A[M,K] @ W[N,K]^T + bias[N]
// MODE 0: scatter epilogue into g_q/g_k/g_v with [B,H,N,hd] layout
// MODE 1: plain row-major store into C
// BM=BN=128, BK=16, 256 threads, 8x8 micro-tile (FFMA2-packed), reg prefetch.
// ---------------------------------------------------------------------------
template<int MODE>
__global__ void __launch_bounds__(256)
gemm_nt(const float* __restrict__ A, const float* __restrict__ W,
        const float* __restrict__ bias, float* __restrict__ C,
        int M, int N, int K)
{
    __shared__ float As[16][128];
    __shared__ float Bs[16][128];

    const int tid = threadIdx.x;
    const int tx = tid & 15, ty = tid >> 4;
    const int bm = blockIdx.y * 128, bn = blockIdx.x * 128;

    const int lrow = tid >> 2;          // 0..63
    const int lc   = (tid & 3) * 4;     // 0,4,8,12
    const float* Ag = A + (size_t)(bm + lrow) * K + lc;
    const float* Wg = W + (size_t)(bn + lrow) * K + lc;
    const size_t strR = (size_t)64 * K;

    float4 a0 = *(const float4*)(Ag);
    float4 a1 = *(const float4*)(Ag + strR);
    float4 b0 = *(const float4*)(Wg);
    float4 b1 = *(const float4*)(Wg + strR);

    u64 acc2[8][4];
#pragma unroll
    for (int i = 0; i < 8; i++)
#pragma unroll
        for (int j = 0; j < 4; j++) acc2[i][j] = 0ULL;

    const int nk = K / 16;
    for (int kt = 0; kt < nk; kt++) {
        As[lc+0][lrow]    = a0.x; As[lc+1][lrow]    = a0.y;
        As[lc+2][lrow]    = a0.z; As[lc+3][lrow]    = a0.w;
        As[lc+0][lrow+64] = a1.x; As[lc+1][lrow+64] = a1.y;
        As[lc+2][lrow+64] = a1.z; As[lc+3][lrow+64] = a1.w;
        Bs[lc+0][lrow]    = b0.x; Bs[lc+1][lrow]    = b0.y;
        Bs[lc+2][lrow]    = b0.z; Bs[lc+3][lrow]    = b0.w;
        Bs[lc+0][lrow+64] = b1.x; Bs[lc+1][lrow+64] = b1.y;
        Bs[lc+2][lrow+64] = b1.z; Bs[lc+3][lrow+64] = b1.w;
        __syncthreads();

        if (kt + 1 < nk) {
            const float* Ag2 = Ag + (size_t)(kt + 1) * 16;
            const float* Wg2 = Wg + (size_t)(kt + 1) * 16;
            a0 = *(const float4*)(Ag2);
            a1 = *(const float4*)(Ag2 + strR);
            b0 = *(const float4*)(Wg2);
            b1 = *(const float4*)(Wg2 + strR);
        }

#pragma unroll
        for (int k = 0; k < 16; k++) {
            float4 af0 = *(const float4*)&As[k][ty * 8];
            float4 af1 = *(const float4*)&As[k][ty * 8 + 4];
            float4 bf0 = *(const float4*)&Bs[k][tx * 8];
            float4 bf1 = *(const float4*)&Bs[k][tx * 8 + 4];
            u64 bv2[4] = {pk2(bf0.x, bf0.y), pk2(bf0.z, bf0.w),
                          pk2(bf1.x, bf1.y), pk2(bf1.z, bf1.w)};
            float av[8] = {af0.x, af0.y, af0.z, af0.w, af1.x, af1.y, af1.z, af1.w};
#pragma unroll
            for (int i = 0; i < 8; i++) {
                const u64 ad = dup2(av[i]);
#pragma unroll
                for (int jp = 0; jp < 4; jp++) fma2(acc2[i][jp], ad, bv2[jp]);
            }
        }
        __syncthreads();
    }

    const int row0 = bm + ty * 8, col0 = bn + tx * 8;
#pragma unroll
    for (int i = 0; i < 8; i++) {
        const int m = row0 + i;
#pragma unroll
        for (int jp = 0; jp < 4; jp++) {
            const float2 v2 = up2(acc2[i][jp]);
#pragma unroll
            for (int h = 0; h < 2; h++) {
                const int n = col0 + jp * 2 + h;
                const float v = (h ? v2.y : v2.x) + __ldg(&bias[n]);
                if (MODE == 0) {
                    const int chunk = n >> 10;          // 0=q 1=k 2=v
                    const int rem = n & 1023;
                    const int hh = rem >> 6, d = rem & 63;
                    const int b = m >> 11, t = m & 2047;
                    float* dst = (chunk == 0) ? g_q : (chunk == 1) ? g_k : g_v;
                    dst[(((size_t)b * NH + hh) * SEQ + t) * HD + d] = v;
                } else {
                    C[(size_t)m * N + n] = v;
                }
            }
        }
    }
}

// ---------------------------------------------------------------------------
// Flash attention fp32, FFMA2-packed, k-major transposed Q/K tiles.
// Block = 128 queries x one (b,h). 256 threads: trow=tid/8 -> 4 q-rows,
// tcol=tid%8 -> 8 key-cols. K-tile = 64 keys. Online softmax, width-8 shuffle.
// ---------------------------------------------------------------------------
#define QT_S 132   // Qt[64][132]  (d-major: Qt[d][q]), stride %4==0 for LDS.128
#define KT_S 68    // Kt[64][68]   (d-major: Kt[d][key])
#define VS_S 68    // Vs[64][68]   (key-major: Vs[key][d])
#define PS_S 66    // Ps[128][66]  (q-major), even stride for STS.64

__global__ void __launch_bounds__(256) attn_kernel()
{
    extern __shared__ float sm[];
    float* Qt = sm;                     // 64 x 132
    float* Kt = Qt + 64 * QT_S;         // 64 x 68
    float* Vs = Kt + 64 * KT_S;         // 64 x 68
    float* Ps = Vs + 64 * VS_S;         // 128 x 66

    const int tid = threadIdx.x;
    const int tcol = tid & 7, trow = tid >> 3;
    const int r0 = trow * 4, c0 = tcol * 8;
    const int bh = blockIdx.y;
    const int q0 = blockIdx.x * 128;

    const float* Qg = g_q + (size_t)bh * SEQ * HD;
    const float* Kg = g_k + (size_t)bh * SEQ * HD;
    const float* Vg = g_v + (size_t)bh * SEQ * HD;

    const float scale = 0.125f;  // HD^-0.5 folded into Q

    // Q -> Qt transposed (2048 float4 loads)
#pragma unroll
    for (int it = 0; it < 8; it++) {
        const int v = tid + 256 * it;
        const int row = v >> 4, c = (v & 15) * 4;
        float4 q4 = *(const float4*)(Qg + (size_t)(q0 + row) * HD + c);
        Qt[(c + 0) * QT_S + row] = q4.x * scale;
        Qt[(c + 1) * QT_S + row] = q4.y * scale;
        Qt[(c + 2) * QT_S + row] = q4.z * scale;
        Qt[(c + 3) * QT_S + row] = q4.w * scale;
    }

    float m_i[4], l_i[4];
    u64 Of2[4][4];
#pragma unroll
    for (int i = 0; i < 4; i++) {
        m_i[i] = -1e30f; l_i[i] = 0.f;
#pragma unroll
        for (int j = 0; j < 4; j++) Of2[i][j] = 0ULL;
    }

    for (int kt = 0; kt < SEQ / 64; kt++) {
        __syncthreads();  // prev PV done (and Q visible on kt=0) before overwrite
#pragma unroll
        for (int it = 0; it < 4; it++) {
            const int v = tid + 256 * it;
            const int row = v >> 4, c = (v & 15) * 4;   // row = key idx
            float4 k4 = *(const float4*)(Kg + (size_t)(kt * 64 + row) * HD + c);
            float4 v4 = *(const float4*)(Vg + (size_t)(kt * 64 + row) * HD + c);
            Kt[(c + 0) * KT_S + row] = k4.x;
            Kt[(c + 1) * KT_S + row] = k4.y;
            Kt[(c + 2) * KT_S + row] = k4.z;
            Kt[(c + 3) * KT_S + row] = k4.w;
            *(float4*)&Vs[row * VS_S + c] = v4;
        }
        __syncthreads();

        // S = Q K^T  (4x8 fragment, packed pairs over key axis)
        u64 s2[4][4];
#pragma unroll
        for (int i = 0; i < 4; i++)
#pragma unroll
            for (int j = 0; j < 4; j++) s2[i][j] = 0ULL;

#pragma unroll 8
        for (int k = 0; k < 64; k++) {
            float4 aq = *(const float4*)&Qt[k * QT_S + r0];
            float4 bk0 = *(const float4*)&Kt[k * KT_S + c0];
            float4 bk1 = *(const float4*)&Kt[k * KT_S + c0 + 4];
            u64 bv2[4] = {pk2(bk0.x, bk0.y), pk2(bk0.z, bk0.w),
                          pk2(bk1.x, bk1.y), pk2(bk1.z, bk1.w)};
            float av[4] = {aq.x, aq.y, aq.z, aq.w};
#pragma unroll
            for (int i = 0; i < 4; i++) {
                const u64 ad = dup2(av[i]);
#pragma unroll
                for (int jp = 0; jp < 4; jp++) fma2(s2[i][jp], ad, bv2[jp]);
            }
        }

        // online softmax
#pragma unroll
        for (int i = 0; i < 4; i++) {
            float s[8];
#pragma unroll
            for (int jp = 0; jp < 4; jp++) {
                float2 f = up2(s2[i][jp]);
                s[jp * 2] = f.x; s[jp * 2 + 1] = f.y;
            }
            float mx = s[0];
#pragma unroll
            for (int j = 1; j < 8; j++) mx = fmaxf(mx, s[j]);
            mx = fmaxf(mx, __shfl_xor_sync(0xffffffffu, mx, 4, 8));
            mx = fmaxf(mx, __shfl_xor_sync(0xffffffffu, mx, 2, 8));
            mx = fmaxf(mx, __shfl_xor_sync(0xffffffffu, mx, 1, 8));
            const float mnew = fmaxf(m_i[i], mx);
            const float alpha = __expf(m_i[i] - mnew);
            float rs = 0.f;
#pragma unroll
            for (int j = 0; j < 8; j++) {
                const float p = __expf(s[j] - mnew);
                s[j] = p; rs += p;
            }
            rs += __shfl_xor_sync(0xffffffffu, rs, 4, 8);
            rs += __shfl_xor_sync(0xffffffffu, rs, 2, 8);
            rs += __shfl_xor_sync(0xffffffffu, rs, 1, 8);
            l_i[i] = l_i[i] * alpha + rs;
            m_i[i] = mnew;
            const u64 al2 = dup2(alpha);
#pragma unroll
            for (int jp = 0; jp < 4; jp++) Of2[i][jp] = mul2(Of2[i][jp], al2);
#pragma unroll
            for (int jp = 0; jp < 4; jp++)
                *(u64*)&Ps[(r0 + i) * PS_S + c0 + jp * 2] = pk2(s[jp*2], s[jp*2+1]);
        }
        __syncthreads();

        // O += P V  (packed pairs over head-dim axis)
#pragma unroll 8
        for (int k = 0; k < 64; k++) {
            float4 vv0 = *(const float4*)&Vs[k * VS_S + c0];
            float4 vv1 = *(const float4*)&Vs[k * VS_S + c0 + 4];
            u64 vv2[4] = {pk2(vv0.x, vv0.y), pk2(vv0.z, vv0.w),
                          pk2(vv1.x, vv1.y), pk2(vv1.z, vv1.w)};
#pragma unroll
            for (int i = 0; i < 4; i++) {
                const u64 pd = dup2(Ps[(r0 + i) * PS_S + k]);
#pragma unroll
                for (int jp = 0; jp < 4; jp++) fma2(Of2[i][jp], pd, vv2[jp]);
            }
        }
    }

    // epilogue -> g_attn in [B, N, H*hd] layout (proj GEMM A operand)
    const int b = bh >> 4, h = bh & 15;
#pragma unroll
    for (int i = 0; i < 4; i++) {
        const float inv = 1.f / l_i[i];
        const int q = q0 + r0 + i;
        float* dst = &g_attn[((size_t)b * SEQ + q) * DM + h * HD + c0];
#pragma unroll
        for (int jp = 0; jp < 4; jp++) {
            float2 f = up2(Of2[i][jp]);
            dst[jp * 2]     = f.x * inv;
            dst[jp * 2 + 1] = f.y * inv;
        }
    }
}

// ---------------------------------------------------------------------------
extern "C" void kernel_launch(void* const* d_in, const int* in_sizes, int n_in,
                              void* d_out, int out_size)
{
    const float* x      = (const float*)d_in[0];
    const float* qkv_w  = (const float*)d_in[1];
    const float* qkv_b  = (const float*)d_in[2];
    const float* proj_w = (const float*)d_in[3];
    const float* proj_b = (const float*)d_in[4];
    float* out = (float*)d_out;

    void* attn_ptr = nullptr;
    cudaGetSymbolAddress(&attn_ptr, g_attn);

    const size_t smem = (size_t)(64 * QT_S + 64 * KT_S + 64 * VS_S + 128 * PS_S)
                        * sizeof(float);  // 102,400 B
    cudaFuncSetAttribute(attn_kernel, cudaFuncAttributeMaxDynamicSharedMemorySize,
                         (int)smem);

    dim3 blk(256);
    gemm_nt<0><<<dim3(3 * DM / 128, MROWS / 128), blk>>>(
        x, qkv_w, qkv_b, nullptr, MROWS, 3 * DM, DM);
    attn_kernel<<<dim3(SEQ / 128, NB * NH), blk, smem>>>();
    gemm_nt<1><<<dim3(DM / 128, MROWS / 128), blk>>>(
        (const float*)attn_ptr, proj_w, proj_b, out, MROWS, DM, DM);
}

// round 4
// speedup vs baseline: 1.3113x; 1.2895x over previous
#include <cuda_runtime.h>
#include <cuda_bf16.h>
#include <cstdint>

#define SEQ  2048
#define DM   1024
#define NH   16
#define HD   64
#define NB   2
#define MROWS (NB*SEQ)

// ---------------- scratch (device globals; no allocation allowed) ----------
__device__ float g_q[(size_t)NB*NH*SEQ*HD];
__device__ float g_k[(size_t)NB*NH*SEQ*HD];
__device__ float g_v[(size_t)NB*NH*SEQ*HD];
__device__ float g_attn[(size_t)NB*SEQ*DM];

#define NX   ((size_t)MROWS*DM)        // 4194304
#define NW   ((size_t)3*DM*DM)         // 3145728
#define NPW  ((size_t)DM*DM)           // 1048576
__device__ __nv_bfloat16 g_xh[NX],  g_xl[NX];
__device__ __nv_bfloat16 g_wh[NW],  g_wl[NW];
__device__ __nv_bfloat16 g_pwh[NPW], g_pwl[NPW];
__device__ __nv_bfloat16 g_ah[NX],  g_al[NX];

// ---------------- PTX helpers ----------------------------------------------
__device__ __forceinline__ uint32_t smem_u32(const void* p) {
    uint32_t a;
    asm("{ .reg .u64 t; cvta.to.shared.u64 t, %1; cvt.u32.u64 %0, t; }"
        : "=r"(a) : "l"(p));
    return a;
}
#define CP16(s, g) \
    asm volatile("cp.async.cg.shared.global [%0], [%1], 16;" :: "r"(s), "l"(g))
#define CP_COMMIT() asm volatile("cp.async.commit_group;" ::: "memory")
#define CP_WAIT1()  asm volatile("cp.async.wait_group 1;" ::: "memory")
#define CP_WAIT0()  asm volatile("cp.async.wait_group 0;" ::: "memory")

__device__ __forceinline__ uint32_t sw128(uint32_t off) {
    return off ^ ((off >> 3) & 0x70);
}
__device__ __forceinline__ void ldm_x4(uint32_t* r, uint32_t a) {
    asm volatile("ldmatrix.sync.aligned.m8n8.x4.shared.b16 {%0,%1,%2,%3}, [%4];"
        : "=r"(r[0]), "=r"(r[1]), "=r"(r[2]), "=r"(r[3]) : "r"(a));
}
__device__ __forceinline__ void mma_bf16(float* c, const uint32_t* a,
                                         const uint32_t* b) {
    asm volatile(
        "mma.sync.aligned.m16n8k16.row.col.f32.bf16.bf16.f32 "
        "{%0,%1,%2,%3}, {%4,%5,%6,%7}, {%8,%9}, {%0,%1,%2,%3};"
        : "+f"(c[0]), "+f"(c[1]), "+f"(c[2]), "+f"(c[3])
        : "r"(a[0]), "r"(a[1]), "r"(a[2]), "r"(a[3]), "r"(b[0]), "r"(b[1]));
}

// ---------------- fp32 -> bf16 hi/lo split ----------------------------------
__global__ void __launch_bounds__(256)
split_bf16(const float* __restrict__ in, __nv_bfloat16* __restrict__ hi,
           __nv_bfloat16* __restrict__ lo, size_t n)
{
    size_t i = ((size_t)blockIdx.x * 256 + threadIdx.x) * 4;
    if (i >= n) return;
    float4 v = *(const float4*)(in + i);
    float f[4] = {v.x, v.y, v.z, v.w};
    __nv_bfloat16 h4[4], l4[4];
#pragma unroll
    for (int j = 0; j < 4; j++) {
        h4[j] = __float2bfloat16(f[j]);
        l4[j] = __float2bfloat16(f[j] - __bfloat162float(h4[j]));
    }
    *(uint2*)(hi + i) = *(uint2*)h4;
    *(uint2*)(lo + i) = *(uint2*)l4;
}

// ---------------------------------------------------------------------------
// mma.sync bf16-split GEMM: C[M,N] = A[M,1024] @ W[N,1024]^T + bias
// CTA tile 128x128, 8 warps (4m x 2n), warp tile 32x64, BK=64 bf16 (SW128).
// 3-term split: Ah*Wh + Ah*Wl + Al*Wh, fp32 accum.
// MODE 0: scatter into g_q/g_k/g_v ([B,H,N,hd]); MODE 1: row-major C.
// ---------------------------------------------------------------------------
#define TILE_B   16384                 // one 128x64 bf16 tile (SW128 rows)
#define STAGE_B  (4 * TILE_B)          // Ah, Al, Wh, Wl

template<int MODE>
__global__ void __launch_bounds__(256)
mma_gemm(const __nv_bfloat16* __restrict__ Ah, const __nv_bfloat16* __restrict__ Al,
         const __nv_bfloat16* __restrict__ Wh, const __nv_bfloat16* __restrict__ Wl,
         const float* __restrict__ bias, float* __restrict__ C, int N)
{
    constexpr int K = 1024, KT = K / 64;
    extern __shared__ char dsm[];
    const uint32_t smb = smem_u32(dsm);

    const int tid = threadIdx.x, lane = tid & 31, wid = tid >> 5;
    const int wm = wid & 3, wn = wid >> 2;            // 4 x 2 warp grid
    const int bn = blockIdx.x * 128, bm = blockIdx.y * 128;

    const __nv_bfloat16* gA[2] = {Ah + (size_t)bm * K, Al + (size_t)bm * K};
    const __nv_bfloat16* gW[2] = {Wh + (size_t)bn * K, Wl + (size_t)bn * K};

    // loader: 16 x CP16 per thread per stage (Ah, Al, Wh, Wl tiles of 128x64)
    auto load_stage = [&](int s, int kt) {
        const uint32_t base = smb + s * STAGE_B;
#pragma unroll
        for (int sel = 0; sel < 4; sel++) {           // 0:Ah 1:Al 2:Wh 3:Wl
            const uint32_t tb = base + sel * TILE_B;
            const __nv_bfloat16* g =
                ((sel < 2) ? gA[sel] : gW[sel - 2]) + (size_t)kt * 64;
#pragma unroll
            for (int i = 0; i < 4; i++) {
                int idx = tid + i * 256;
                int r = idx >> 3, seg = idx & 7;
                CP16(tb + sw128(r * 128 + seg * 16), g + (size_t)r * K + seg * 8);
            }
        }
        CP_COMMIT();
    };

    float acc[2][8][4];
#pragma unroll
    for (int mt = 0; mt < 2; mt++)
#pragma unroll
        for (int nt = 0; nt < 8; nt++)
#pragma unroll
            for (int j = 0; j < 4; j++) acc[mt][nt][j] = 0.f;

    // per-lane ldmatrix geometry (byte offsets before swizzle)
    const int a_row = wm * 32 + (lane & 15);          // + mt*16
    const int a_kb  = (lane >> 4) * 16;               // + ks*32
    const int b_row = wn * 64 + (lane & 7) + ((lane >> 4) << 3);  // + ng*16
    const int b_kb  = ((lane >> 3) & 1) * 16;         // + ks*32

    load_stage(0, 0);
    load_stage(1, 1);

    for (int t = 0; t < KT; t++) {
        const int s = t & 1;
        if (t == KT - 1) { CP_WAIT0(); } else { CP_WAIT1(); }
        __syncthreads();

        const uint32_t bAh = smb + s * STAGE_B;
        const uint32_t bAl = bAh + TILE_B;
        const uint32_t bWh = bAh + 2 * TILE_B;
        const uint32_t bWl = bAh + 3 * TILE_B;

#pragma unroll
        for (int ks = 0; ks < 4; ks++) {
            uint32_t afh[2][4], afl[2][4];
#pragma unroll
            for (int mt = 0; mt < 2; mt++) {
                const uint32_t off = (a_row + mt * 16) * 128 + a_kb + ks * 32;
                ldm_x4(afh[mt], bAh + sw128(off));
                ldm_x4(afl[mt], bAl + sw128(off));
            }
            uint32_t bfh[4][4], bfl[4][4];
#pragma unroll
            for (int ng = 0; ng < 4; ng++) {
                const uint32_t off = (b_row + ng * 16) * 128 + b_kb + ks * 32;
                ldm_x4(bfh[ng], bWh + sw128(off));
                ldm_x4(bfl[ng], bWl + sw128(off));
            }
#pragma unroll
            for (int mt = 0; mt < 2; mt++)
#pragma unroll
                for (int nt = 0; nt < 8; nt++) {
                    const int ng = nt >> 1, hp = (nt & 1) * 2;
                    mma_bf16(acc[mt][nt], afh[mt], &bfh[ng][hp]);
                    mma_bf16(acc[mt][nt], afh[mt], &bfl[ng][hp]);
                    mma_bf16(acc[mt][nt], afl[mt], &bfh[ng][hp]);
                }
        }
        __syncthreads();
        if (t + 2 < KT) load_stage(s, t + 2);
    }

    // epilogue: C frag thread layout: rows lane/4 (+8), cols 2*(lane%4) (+1)
    const int gr = lane >> 2, gc = (lane & 3) * 2;
#pragma unroll
    for (int mt = 0; mt < 2; mt++) {
#pragma unroll
        for (int half = 0; half < 2; half++) {
            const int m = bm + wm * 32 + mt * 16 + gr + half * 8;
#pragma unroll
            for (int nt = 0; nt < 8; nt++) {
                const int n = bn + wn * 64 + nt * 8 + gc;
                float2 v;
                v.x = acc[mt][nt][half * 2 + 0] + __ldg(bias + n);
                v.y = acc[mt][nt][half * 2 + 1] + __ldg(bias + n + 1);
                if (MODE == 0) {
                    const int chunk = n >> 10, rem = n & 1023;
                    const int h = rem >> 6, d = rem & 63;
                    const int b = m >> 11, tt = m & 2047;
                    float* dst = (chunk == 0) ? g_q : (chunk == 1) ? g_k : g_v;
                    *(float2*)&dst[(((size_t)b * NH + h) * SEQ + tt) * HD + d] = v;
                } else {
                    *(float2*)&C[(size_t)m * N + n] = v;
                }
            }
        }
    }
}

// ---------------------------------------------------------------------------
// Flash attention fp32 (round-2 version, passing; mma.sync next round).
// ---------------------------------------------------------------------------
typedef unsigned long long u64;
__device__ __forceinline__ u64 pk2(float a, float b) {
    u64 r; asm("mov.b64 %0,{%1,%2};" : "=l"(r) : "f"(a), "f"(b)); return r;
}
__device__ __forceinline__ u64 dup2(float a) {
    u64 r; asm("mov.b64 %0,{%1,%1};" : "=l"(r) : "f"(a)); return r;
}
__device__ __forceinline__ void fma2(u64& d, u64 a, u64 b) {
    asm("fma.rn.f32x2 %0,%1,%2,%0;" : "+l"(d) : "l"(a), "l"(b));
}
__device__ __forceinline__ u64 mul2(u64 a, u64 b) {
    u64 r; asm("mul.rn.f32x2 %0,%1,%2;" : "=l"(r) : "l"(a), "l"(b)); return r;
}
__device__ __forceinline__ float2 up2(u64 v) {
    float2 f; asm("mov.b64 {%0,%1},%2;" : "=f"(f.x), "=f"(f.y) : "l"(v)); return f;
}

#define QT_S 132
#define KT_S 68
#define VS_S 68
#define PS_S 66

__global__ void __launch_bounds__(256) attn_kernel()
{
    extern __shared__ float sm[];
    float* Qt = sm;
    float* Kt = Qt + 64 * QT_S;
    float* Vs = Kt + 64 * KT_S;
    float* Ps = Vs + 64 * VS_S;

    const int tid = threadIdx.x;
    const int tcol = tid & 7, trow = tid >> 3;
    const int r0 = trow * 4, c0 = tcol * 8;
    const int bh = blockIdx.y;
    const int q0 = blockIdx.x * 128;

    const float* Qg = g_q + (size_t)bh * SEQ * HD;
    const float* Kg = g_k + (size_t)bh * SEQ * HD;
    const float* Vg = g_v + (size_t)bh * SEQ * HD;

    const float scale = 0.125f;

#pragma unroll
    for (int it = 0; it < 8; it++) {
        const int v = tid + 256 * it;
        const int row = v >> 4, c = (v & 15) * 4;
        float4 q4 = *(const float4*)(Qg + (size_t)(q0 + row) * HD + c);
        Qt[(c + 0) * QT_S + row] = q4.x * scale;
        Qt[(c + 1) * QT_S + row] = q4.y * scale;
        Qt[(c + 2) * QT_S + row] = q4.z * scale;
        Qt[(c + 3) * QT_S + row] = q4.w * scale;
    }

    float m_i[4], l_i[4];
    u64 Of2[4][4];
#pragma unroll
    for (int i = 0; i < 4; i++) {
        m_i[i] = -1e30f; l_i[i] = 0.f;
#pragma unroll
        for (int j = 0; j < 4; j++) Of2[i][j] = 0ULL;
    }

    for (int kt = 0; kt < SEQ / 64; kt++) {
        __syncthreads();
#pragma unroll
        for (int it = 0; it < 4; it++) {
            const int v = tid + 256 * it;
            const int row = v >> 4, c = (v & 15) * 4;
            float4 k4 = *(const float4*)(Kg + (size_t)(kt * 64 + row) * HD + c);
            float4 v4 = *(const float4*)(Vg + (size_t)(kt * 64 + row) * HD + c);
            Kt[(c + 0) * KT_S + row] = k4.x;
            Kt[(c + 1) * KT_S + row] = k4.y;
            Kt[(c + 2) * KT_S + row] = k4.z;
            Kt[(c + 3) * KT_S + row] = k4.w;
            *(float4*)&Vs[row * VS_S + c] = v4;
        }
        __syncthreads();

        u64 s2[4][4];
#pragma unroll
        for (int i = 0; i < 4; i++)
#pragma unroll
            for (int j = 0; j < 4; j++) s2[i][j] = 0ULL;

#pragma unroll 8
        for (int k = 0; k < 64; k++) {
            float4 aq = *(const float4*)&Qt[k * QT_S + r0];
            float4 bk0 = *(const float4*)&Kt[k * KT_S + c0];
            float4 bk1 = *(const float4*)&Kt[k * KT_S + c0 + 4];
            u64 bv2[4] = {pk2(bk0.x, bk0.y), pk2(bk0.z, bk0.w),
                          pk2(bk1.x, bk1.y), pk2(bk1.z, bk1.w)};
            float av[4] = {aq.x, aq.y, aq.z, aq.w};
#pragma unroll
            for (int i = 0; i < 4; i++) {
                const u64 ad = dup2(av[i]);
#pragma unroll
                for (int jp = 0; jp < 4; jp++) fma2(s2[i][jp], ad, bv2[jp]);
            }
        }

#pragma unroll
        for (int i = 0; i < 4; i++) {
            float s[8];
#pragma unroll
            for (int jp = 0; jp < 4; jp++) {
                float2 f = up2(s2[i][jp]);
                s[jp * 2] = f.x; s[jp * 2 + 1] = f.y;
            }
            float mx = s[0];
#pragma unroll
            for (int j = 1; j < 8; j++) mx = fmaxf(mx, s[j]);
            mx = fmaxf(mx, __shfl_xor_sync(0xffffffffu, mx, 4, 8));
            mx = fmaxf(mx, __shfl_xor_sync(0xffffffffu, mx, 2, 8));
            mx = fmaxf(mx, __shfl_xor_sync(0xffffffffu, mx, 1, 8));
            const float mnew = fmaxf(m_i[i], mx);
            const float alpha = __expf(m_i[i] - mnew);
            float rs = 0.f;
#pragma unroll
            for (int j = 0; j < 8; j++) {
                const float p = __expf(s[j] - mnew);
                s[j] = p; rs += p;
            }
            rs += __shfl_xor_sync(0xffffffffu, rs, 4, 8);
            rs += __shfl_xor_sync(0xffffffffu, rs, 2, 8);
            rs += __shfl_xor_sync(0xffffffffu, rs, 1, 8);
            l_i[i] = l_i[i] * alpha + rs;
            m_i[i] = mnew;
            const u64 al2 = dup2(alpha);
#pragma unroll
            for (int jp = 0; jp < 4; jp++) Of2[i][jp] = mul2(Of2[i][jp], al2);
#pragma unroll
            for (int jp = 0; jp < 4; jp++)
                *(u64*)&Ps[(r0 + i) * PS_S + c0 + jp * 2] = pk2(s[jp*2], s[jp*2+1]);
        }
        __syncthreads();

#pragma unroll 8
        for (int k = 0; k < 64; k++) {
            float4 vv0 = *(const float4*)&Vs[k * VS_S + c0];
            float4 vv1 = *(const float4*)&Vs[k * VS_S + c0 + 4];
            u64 vv2[4] = {pk2(vv0.x, vv0.y), pk2(vv0.z, vv0.w),
                          pk2(vv1.x, vv1.y), pk2(vv1.z, vv1.w)};
#pragma unroll
            for (int i = 0; i < 4; i++) {
                const u64 pd = dup2(Ps[(r0 + i) * PS_S + k]);
#pragma unroll
                for (int jp = 0; jp < 4; jp++) fma2(Of2[i][jp], pd, vv2[jp]);
            }
        }
    }

    const int b = bh >> 4, h = bh & 15;
#pragma unroll
    for (int i = 0; i < 4; i++) {
        const float inv = 1.f / l_i[i];
        const int q = q0 + r0 + i;
        float* dst = &g_attn[((size_t)b * SEQ + q) * DM + h * HD + c0];
#pragma unroll
        for (int jp = 0; jp < 4; jp++) {
            float2 f = up2(Of2[i][jp]);
            dst[jp * 2]     = f.x * inv;
            dst[jp * 2 + 1] = f.y * inv;
        }
    }
}

// ---------------------------------------------------------------------------
extern "C" void kernel_launch(void* const* d_in, const int* in_sizes, int n_in,
                              void* d_out, int out_size)
{
    const float* x      = (const float*)d_in[0];
    const float* qkv_w  = (const float*)d_in[1];
    const float* qkv_b  = (const float*)d_in[2];
    const float* proj_w = (const float*)d_in[3];
    const float* proj_b = (const float*)d_in[4];
    float* out = (float*)d_out;

    void *attn_p, *xh, *xl, *wh, *wl, *pwh, *pwl, *ah, *al;
    cudaGetSymbolAddress(&attn_p, g_attn);
    cudaGetSymbolAddress(&xh, g_xh);   cudaGetSymbolAddress(&xl, g_xl);
    cudaGetSymbolAddress(&wh, g_wh);   cudaGetSymbolAddress(&wl, g_wl);
    cudaGetSymbolAddress(&pwh, g_pwh); cudaGetSymbolAddress(&pwl, g_pwl);
    cudaGetSymbolAddress(&ah, g_ah);   cudaGetSymbolAddress(&al, g_al);

    const size_t asmem = (size_t)(64*QT_S + 64*KT_S + 64*VS_S + 128*PS_S) * 4;
    cudaFuncSetAttribute(attn_kernel, cudaFuncAttributeMaxDynamicSharedMemorySize,
                         (int)asmem);
    const int gsmem = 2 * STAGE_B;   // 131072
    cudaFuncSetAttribute(mma_gemm<0>, cudaFuncAttributeMaxDynamicSharedMemorySize, gsmem);
    cudaFuncSetAttribute(mma_gemm<1>, cudaFuncAttributeMaxDynamicSharedMemorySize, gsmem);

    dim3 blk(256);
    split_bf16<<<(unsigned)(NX / 4 / 256), blk>>>(x, (__nv_bfloat16*)xh,
                                                  (__nv_bfloat16*)xl, NX);
    split_bf16<<<(unsigned)(NW / 4 / 256), blk>>>(qkv_w, (__nv_bfloat16*)wh,
                                                  (__nv_bfloat16*)wl, NW);
    split_bf16<<<(unsigned)(NPW / 4 / 256), blk>>>(proj_w, (__nv_bfloat16*)pwh,
                                                   (__nv_bfloat16*)pwl, NPW);
    mma_gemm<0><<<dim3(3 * DM / 128, MROWS / 128), blk, gsmem>>>(
        (const __nv_bfloat16*)xh, (const __nv_bfloat16*)xl,
        (const __nv_bfloat16*)wh, (const __nv_bfloat16*)wl,
        qkv_b, nullptr, 3 * DM);
    attn_kernel<<<dim3(SEQ / 128, NB * NH), blk, asmem>>>();
    split_bf16<<<(unsigned)(NX / 4 / 256), blk>>>((const float*)attn_p,
                                                  (__nv_bfloat16*)ah,
                                                  (__nv_bfloat16*)al, NX);
    mma_gemm<1><<<dim3(DM / 128, MROWS / 128), blk, gsmem>>>(
        (const __nv_bfloat16*)ah, (const __nv_bfloat16*)al,
        (const __nv_bfloat16*)pwh, (const __nv_bfloat16*)pwl,
        proj_b, out, DM);
}

// round 5
// speedup vs baseline: 3.8002x; 2.8981x over previous
#include <cuda_runtime.h>
#include <cuda_bf16.h>
#include <cstdint>

#define SEQ  2048
#define DM   1024
#define NH   16
#define HD   64
#define NB   2
#define MROWS (NB*SEQ)

// ---------------- scratch (device globals; no allocation allowed) ----------
#define NX   ((size_t)MROWS*DM)        // 4194304
#define NW   ((size_t)3*DM*DM)         // 3145728
#define NPW  ((size_t)DM*DM)           // 1048576
#define NQKV ((size_t)NB*NH*SEQ*HD)    // 4194304

__device__ __nv_bfloat16 g_xh[NX],  g_xl[NX];
__device__ __nv_bfloat16 g_wh[NW],  g_wl[NW];
__device__ __nv_bfloat16 g_pwh[NPW], g_pwl[NPW];
__device__ __nv_bfloat16 g_ah[NX],  g_al[NX];
__device__ __nv_bfloat16 g_qh[NQKV], g_ql[NQKV];
__device__ __nv_bfloat16 g_kh[NQKV], g_kl[NQKV];
__device__ __nv_bfloat16 g_vh[NQKV], g_vl[NQKV];

// ---------------- PTX helpers ----------------------------------------------
__device__ __forceinline__ uint32_t smem_u32(const void* p) {
    uint32_t a;
    asm("{ .reg .u64 t; cvta.to.shared.u64 t, %1; cvt.u32.u64 %0, t; }"
        : "=r"(a) : "l"(p));
    return a;
}
#define CP16(s, g) \
    asm volatile("cp.async.cg.shared.global [%0], [%1], 16;" :: "r"(s), "l"(g))
#define CP_COMMIT() asm volatile("cp.async.commit_group;" ::: "memory")
#define CP_WAIT1()  asm volatile("cp.async.wait_group 1;" ::: "memory")
#define CP_WAIT0()  asm volatile("cp.async.wait_group 0;" ::: "memory")

__device__ __forceinline__ uint32_t sw128(uint32_t off) {
    return off ^ ((off >> 3) & 0x70);
}
__device__ __forceinline__ void ldm_x4(uint32_t* r, uint32_t a) {
    asm volatile("ldmatrix.sync.aligned.m8n8.x4.shared.b16 {%0,%1,%2,%3}, [%4];"
        : "=r"(r[0]), "=r"(r[1]), "=r"(r[2]), "=r"(r[3]) : "r"(a));
}
__device__ __forceinline__ void ldm_x4t(uint32_t* r, uint32_t a) {
    asm volatile("ldmatrix.sync.aligned.m8n8.x4.trans.shared.b16 {%0,%1,%2,%3}, [%4];"
        : "=r"(r[0]), "=r"(r[1]), "=r"(r[2]), "=r"(r[3]) : "r"(a));
}
__device__ __forceinline__ void mma_bf16(float* c, const uint32_t* a,
                                         const uint32_t* b) {
    asm volatile(
        "mma.sync.aligned.m16n8k16.row.col.f32.bf16.bf16.f32 "
        "{%0,%1,%2,%3}, {%4,%5,%6,%7}, {%8,%9}, {%0,%1,%2,%3};"
        : "+f"(c[0]), "+f"(c[1]), "+f"(c[2]), "+f"(c[3])
        : "r"(a[0]), "r"(a[1]), "r"(a[2]), "r"(a[3]), "r"(b[0]), "r"(b[1]));
}
// pack {lo, hi} floats -> bf16x2 register
__device__ __forceinline__ uint32_t cvt2(float hi, float lo) {
    uint32_t r;
    asm("cvt.rn.bf16x2.f32 %0, %1, %2;" : "=r"(r) : "f"(hi), "f"(lo));
    return r;
}

// ---------------- fp32 -> bf16 hi/lo split ----------------------------------
__global__ void __launch_bounds__(256)
split_bf16(const float* __restrict__ in, __nv_bfloat16* __restrict__ hi,
           __nv_bfloat16* __restrict__ lo, size_t n)
{
    size_t i = ((size_t)blockIdx.x * 256 + threadIdx.x) * 4;
    if (i >= n) return;
    float4 v = *(const float4*)(in + i);
    float f[4] = {v.x, v.y, v.z, v.w};
    __nv_bfloat16 h4[4], l4[4];
#pragma unroll
    for (int j = 0; j < 4; j++) {
        h4[j] = __float2bfloat16(f[j]);
        l4[j] = __float2bfloat16(f[j] - __bfloat162float(h4[j]));
    }
    *(uint2*)(hi + i) = *(uint2*)h4;
    *(uint2*)(lo + i) = *(uint2*)l4;
}

// ---------------------------------------------------------------------------
// mma.sync bf16-split GEMM: C[M,N] = A[M,1024] @ W[N,1024]^T + bias
// CTA 128x128, 8 warps (4m x 2n), warp tile 32x64, BK=64 bf16 (SW128 smem).
// MODE 0: split + scatter into g_{q,k,v}{h,l} bf16 ([B,H,N,hd]), Q scaled 0.125
// MODE 1: row-major fp32 C
// ---------------------------------------------------------------------------
#define TILE_B   16384
#define STAGE_B  (4 * TILE_B)

template<int MODE>
__global__ void __launch_bounds__(256)
mma_gemm(const __nv_bfloat16* __restrict__ Ah, const __nv_bfloat16* __restrict__ Al,
         const __nv_bfloat16* __restrict__ Wh, const __nv_bfloat16* __restrict__ Wl,
         const float* __restrict__ bias, float* __restrict__ C, int N)
{
    constexpr int K = 1024, KT = K / 64;
    extern __shared__ char dsm[];
    const uint32_t smb = smem_u32(dsm);

    const int tid = threadIdx.x, lane = tid & 31, wid = tid >> 5;
    const int wm = wid & 3, wn = wid >> 2;
    const int bn = blockIdx.x * 128, bm = blockIdx.y * 128;

    const __nv_bfloat16* gA[2] = {Ah + (size_t)bm * K, Al + (size_t)bm * K};
    const __nv_bfloat16* gW[2] = {Wh + (size_t)bn * K, Wl + (size_t)bn * K};

    auto load_stage = [&](int s, int kt) {
        const uint32_t base = smb + s * STAGE_B;
#pragma unroll
        for (int sel = 0; sel < 4; sel++) {
            const uint32_t tb = base + sel * TILE_B;
            const __nv_bfloat16* g =
                ((sel < 2) ? gA[sel] : gW[sel - 2]) + (size_t)kt * 64;
#pragma unroll
            for (int i = 0; i < 4; i++) {
                int idx = tid + i * 256;
                int r = idx >> 3, seg = idx & 7;
                CP16(tb + sw128(r * 128 + seg * 16), g + (size_t)r * K + seg * 8);
            }
        }
        CP_COMMIT();
    };

    float acc[2][8][4];
#pragma unroll
    for (int mt = 0; mt < 2; mt++)
#pragma unroll
        for (int nt = 0; nt < 8; nt++)
#pragma unroll
            for (int j = 0; j < 4; j++) acc[mt][nt][j] = 0.f;

    const int a_row = wm * 32 + (lane & 15);
    const int a_kb  = (lane >> 4) * 16;
    const int b_row = wn * 64 + (lane & 7) + ((lane >> 4) << 3);
    const int b_kb  = ((lane >> 3) & 1) * 16;

    load_stage(0, 0);
    load_stage(1, 1);

    for (int t = 0; t < KT; t++) {
        const int s = t & 1;
        if (t == KT - 1) { CP_WAIT0(); } else { CP_WAIT1(); }
        __syncthreads();

        const uint32_t bAh = smb + s * STAGE_B;
        const uint32_t bAl = bAh + TILE_B;
        const uint32_t bWh = bAh + 2 * TILE_B;
        const uint32_t bWl = bAh + 3 * TILE_B;

#pragma unroll
        for (int ks = 0; ks < 4; ks++) {
            uint32_t afh[2][4], afl[2][4];
#pragma unroll
            for (int mt = 0; mt < 2; mt++) {
                const uint32_t off = (a_row + mt * 16) * 128 + a_kb + ks * 32;
                ldm_x4(afh[mt], bAh + sw128(off));
                ldm_x4(afl[mt], bAl + sw128(off));
            }
            uint32_t bfh[4][4], bfl[4][4];
#pragma unroll
            for (int ng = 0; ng < 4; ng++) {
                const uint32_t off = (b_row + ng * 16) * 128 + b_kb + ks * 32;
                ldm_x4(bfh[ng], bWh + sw128(off));
                ldm_x4(bfl[ng], bWl + sw128(off));
            }
#pragma unroll
            for (int mt = 0; mt < 2; mt++)
#pragma unroll
                for (int nt = 0; nt < 8; nt++) {
                    const int ng = nt >> 1, hp = (nt & 1) * 2;
                    mma_bf16(acc[mt][nt], afh[mt], &bfh[ng][hp]);
                    mma_bf16(acc[mt][nt], afh[mt], &bfl[ng][hp]);
                    mma_bf16(acc[mt][nt], afl[mt], &bfh[ng][hp]);
                }
        }
        __syncthreads();
        if (t + 2 < KT) load_stage(s, t + 2);
    }

    const int gr = lane >> 2, gc = (lane & 3) * 2;
#pragma unroll
    for (int mt = 0; mt < 2; mt++) {
#pragma unroll
        for (int half = 0; half < 2; half++) {
            const int m = bm + wm * 32 + mt * 16 + gr + half * 8;
#pragma unroll
            for (int nt = 0; nt < 8; nt++) {
                const int n = bn + wn * 64 + nt * 8 + gc;
                float vx = acc[mt][nt][half * 2 + 0] + __ldg(bias + n);
                float vy = acc[mt][nt][half * 2 + 1] + __ldg(bias + n + 1);
                if (MODE == 0) {
                    const int chunk = n >> 10, rem = n & 1023;
                    const int h = rem >> 6, d = rem & 63;
                    const int b = m >> 11, tt = m & 2047;
                    if (chunk == 0) { vx *= 0.125f; vy *= 0.125f; }
                    __nv_bfloat16 hx = __float2bfloat16(vx);
                    __nv_bfloat16 hy = __float2bfloat16(vy);
                    __nv_bfloat16 lx = __float2bfloat16(vx - __bfloat162float(hx));
                    __nv_bfloat16 ly = __float2bfloat16(vy - __bfloat162float(hy));
                    __nv_bfloat16* dh = (chunk == 0) ? g_qh : (chunk == 1) ? g_kh : g_vh;
                    __nv_bfloat16* dl = (chunk == 0) ? g_ql : (chunk == 1) ? g_kl : g_vl;
                    const size_t off = (((size_t)b * NH + h) * SEQ + tt) * HD + d;
                    __nv_bfloat162 ph; ph.x = hx; ph.y = hy;
                    __nv_bfloat162 pl; pl.x = lx; pl.y = ly;
                    *(__nv_bfloat162*)&dh[off] = ph;
                    *(__nv_bfloat162*)&dl[off] = pl;
                } else {
                    float2 v; v.x = vx; v.y = vy;
                    *(float2*)&C[(size_t)m * N + n] = v;
                }
            }
        }
    }
}

// ---------------------------------------------------------------------------
// mma.sync flash attention, bf16 3-term split, register-resident P.
// CTA: 128 queries x one (b,h); 8 warps x 16 q-rows; 64-key tiles,
// double-buffered cp.async. Output written as bf16 hi/lo into g_ah/g_al.
// smem: Qh 16K | Ql 16K | 2 stages x {Kh,Kl,Vh,Vl} 8K each = 96 KB.
// ---------------------------------------------------------------------------
#define KVSTG 32768

__global__ void __launch_bounds__(256, 2) attn_mma()
{
    extern __shared__ char axm[];
    const uint32_t smb = smem_u32(axm);
    const int tid = threadIdx.x, lane = tid & 31, wid = tid >> 5;
    const int bh = blockIdx.y, q0 = blockIdx.x * 128;
    const int wq = wid * 16;

    const size_t gbase = (size_t)bh * SEQ * HD;
    const __nv_bfloat16* pQh = g_qh + gbase + (size_t)q0 * HD;
    const __nv_bfloat16* pQl = g_ql + gbase + (size_t)q0 * HD;

    // Q tiles (hi/lo), 128 rows x 128B, SW128
#pragma unroll
    for (int i = 0; i < 4; i++) {
        int idx = tid + i * 256;
        int r = idx >> 3, seg = idx & 7;
        CP16(smb + sw128(r * 128 + seg * 16), pQh + (size_t)r * HD + seg * 8);
        CP16(smb + 16384 + sw128(r * 128 + seg * 16), pQl + (size_t)r * HD + seg * 8);
    }

    const __nv_bfloat16* gkv[4] = {g_kh + gbase, g_kl + gbase,
                                   g_vh + gbase, g_vl + gbase};
    auto load_kv = [&](int s, int it) {
        const uint32_t base = smb + 32768 + s * KVSTG;
#pragma unroll
        for (int sel = 0; sel < 4; sel++) {
            const __nv_bfloat16* g = gkv[sel] + (size_t)it * 64 * HD;
#pragma unroll
            for (int i = 0; i < 2; i++) {
                int idx = tid + i * 256;
                int r = idx >> 3, seg = idx & 7;
                CP16(base + sel * 8192 + sw128(r * 128 + seg * 16),
                     g + (size_t)r * HD + seg * 8);
            }
        }
        CP_COMMIT();
    };
    load_kv(0, 0);   // group 0 also contains the Q loads above
    load_kv(1, 1);

    // fragment geometry
    const int a_row = wq + (lane & 15);
    const int a_kb  = (lane >> 4) * 16;
    const int b_row = (lane & 7) + ((lane >> 4) << 3);
    const int b_kb  = ((lane >> 3) & 1) * 16;
    const int v_row = (lane & 7) + (((lane >> 3) & 1) << 3);
    const int v_cb  = (lane >> 4) * 16;

    float sO[8][4];
#pragma unroll
    for (int nt = 0; nt < 8; nt++)
#pragma unroll
        for (int j = 0; j < 4; j++) sO[nt][j] = 0.f;
    float m0 = -1e30f, m1 = -1e30f, l0 = 0.f, l1 = 0.f;

    for (int it = 0; it < SEQ / 64; it++) {
        const int s = it & 1;
        if (it == SEQ / 64 - 1) { CP_WAIT0(); } else { CP_WAIT1(); }
        __syncthreads();

        const uint32_t bKh = smb + 32768 + s * KVSTG;
        const uint32_t bKl = bKh + 8192;
        const uint32_t bVh = bKh + 16384;
        const uint32_t bVl = bKh + 24576;

        // ---- S = Q K^T (16 q x 64 keys per warp), 3-term split ----
        float sS[8][4];
#pragma unroll
        for (int nt = 0; nt < 8; nt++)
#pragma unroll
            for (int j = 0; j < 4; j++) sS[nt][j] = 0.f;

#pragma unroll
        for (int ks = 0; ks < 4; ks++) {
            uint32_t qh[4], ql[4];
            const uint32_t aoff = sw128(a_row * 128 + a_kb + ks * 32);
            ldm_x4(qh, smb + aoff);
            ldm_x4(ql, smb + 16384 + aoff);
#pragma unroll
            for (int ng = 0; ng < 4; ng++) {
                uint32_t kh[4], kl[4];
                const uint32_t off = sw128((ng * 16 + b_row) * 128 + b_kb + ks * 32);
                ldm_x4(kh, bKh + off);
                ldm_x4(kl, bKl + off);
                mma_bf16(sS[2*ng],   qh, &kh[0]);
                mma_bf16(sS[2*ng],   qh, &kl[0]);
                mma_bf16(sS[2*ng],   ql, &kh[0]);
                mma_bf16(sS[2*ng+1], qh, &kh[2]);
                mma_bf16(sS[2*ng+1], qh, &kl[2]);
                mma_bf16(sS[2*ng+1], ql, &kh[2]);
            }
        }

        // ---- online softmax (rows r=lane>>2 and r+8) ----
        float mx0 = -1e30f, mx1 = -1e30f;
#pragma unroll
        for (int nt = 0; nt < 8; nt++) {
            mx0 = fmaxf(mx0, fmaxf(sS[nt][0], sS[nt][1]));
            mx1 = fmaxf(mx1, fmaxf(sS[nt][2], sS[nt][3]));
        }
        mx0 = fmaxf(mx0, __shfl_xor_sync(0xffffffffu, mx0, 1));
        mx0 = fmaxf(mx0, __shfl_xor_sync(0xffffffffu, mx0, 2));
        mx1 = fmaxf(mx1, __shfl_xor_sync(0xffffffffu, mx1, 1));
        mx1 = fmaxf(mx1, __shfl_xor_sync(0xffffffffu, mx1, 2));
        const float mn0 = fmaxf(m0, mx0), mn1 = fmaxf(m1, mx1);
        const float al0 = __expf(m0 - mn0), al1 = __expf(m1 - mn1);
        float rs0 = 0.f, rs1 = 0.f;
#pragma unroll
        for (int nt = 0; nt < 8; nt++) {
            sS[nt][0] = __expf(sS[nt][0] - mn0);
            sS[nt][1] = __expf(sS[nt][1] - mn0);
            sS[nt][2] = __expf(sS[nt][2] - mn1);
            sS[nt][3] = __expf(sS[nt][3] - mn1);
            rs0 += sS[nt][0] + sS[nt][1];
            rs1 += sS[nt][2] + sS[nt][3];
        }
        rs0 += __shfl_xor_sync(0xffffffffu, rs0, 1);
        rs0 += __shfl_xor_sync(0xffffffffu, rs0, 2);
        rs1 += __shfl_xor_sync(0xffffffffu, rs1, 1);
        rs1 += __shfl_xor_sync(0xffffffffu, rs1, 2);
        l0 = l0 * al0 + rs0;  m0 = mn0;
        l1 = l1 * al1 + rs1;  m1 = mn1;
#pragma unroll
        for (int nt = 0; nt < 8; nt++) {
            sO[nt][0] *= al0; sO[nt][1] *= al0;
            sO[nt][2] *= al1; sO[nt][3] *= al1;
        }

        // ---- O += P V (P in registers, split hi/lo) ----
#pragma unroll
        for (int ks = 0; ks < 4; ks++) {
            const float* t0 = sS[2 * ks];
            const float* t1 = sS[2 * ks + 1];
            uint32_t ph[4], pl[4];
            const float src[8] = {t0[0], t0[1], t0[2], t0[3],
                                  t1[0], t1[1], t1[2], t1[3]};
#pragma unroll
            for (int j = 0; j < 4; j++) {
                const float p0 = src[j * 2], p1 = src[j * 2 + 1];
                const uint32_t hp = cvt2(p1, p0);
                ph[j] = hp;
                const float f0 = __uint_as_float(hp << 16);
                const float f1 = __uint_as_float(hp & 0xffff0000u);
                pl[j] = cvt2(p1 - f1, p0 - f0);
            }
#pragma unroll
            for (int dg = 0; dg < 4; dg++) {
                uint32_t vh[4], vl[4];
                const uint32_t off = sw128((ks * 16 + v_row) * 128 + dg * 32 + v_cb);
                ldm_x4t(vh, bVh + off);
                ldm_x4t(vl, bVl + off);
                mma_bf16(sO[2*dg],   ph, &vh[0]);
                mma_bf16(sO[2*dg],   ph, &vl[0]);
                mma_bf16(sO[2*dg],   pl, &vh[0]);
                mma_bf16(sO[2*dg+1], ph, &vh[2]);
                mma_bf16(sO[2*dg+1], ph, &vl[2]);
                mma_bf16(sO[2*dg+1], pl, &vh[2]);
            }
        }

        __syncthreads();   // all warps done reading stage s
        if (it + 2 < SEQ / 64) load_kv(s, it + 2);
    }

    // ---- epilogue: O/l -> bf16 hi/lo into g_ah/g_al ([B,N,H*hd]) ----
    const float inv0 = 1.f / l0, inv1 = 1.f / l1;
    const int b = bh >> 4, h = bh & 15;
    const int qr = q0 + wq + (lane >> 2);
    const int dc = (lane & 3) * 2;
    const size_t base0 = ((size_t)b * SEQ + qr) * DM + h * HD + dc;
    const size_t base1 = base0 + (size_t)8 * DM;
#pragma unroll
    for (int nt = 0; nt < 8; nt++) {
        const float v0 = sO[nt][0] * inv0, v1 = sO[nt][1] * inv0;
        const float v2 = sO[nt][2] * inv1, v3 = sO[nt][3] * inv1;
        uint32_t h01 = cvt2(v1, v0);
        uint32_t l01 = cvt2(v1 - __uint_as_float(h01 & 0xffff0000u),
                            v0 - __uint_as_float(h01 << 16));
        uint32_t h23 = cvt2(v3, v2);
        uint32_t l23 = cvt2(v3 - __uint_as_float(h23 & 0xffff0000u),
                            v2 - __uint_as_float(h23 << 16));
        *(uint32_t*)&g_ah[base0 + nt * 8] = h01;
        *(uint32_t*)&g_al[base0 + nt * 8] = l01;
        *(uint32_t*)&g_ah[base1 + nt * 8] = h23;
        *(uint32_t*)&g_al[base1 + nt * 8] = l23;
    }
}

// ---------------------------------------------------------------------------
extern "C" void kernel_launch(void* const* d_in, const int* in_sizes, int n_in,
                              void* d_out, int out_size)
{
    const float* x      = (const float*)d_in[0];
    const float* qkv_w  = (const float*)d_in[1];
    const float* qkv_b  = (const float*)d_in[2];
    const float* proj_w = (const float*)d_in[3];
    const float* proj_b = (const float*)d_in[4];
    float* out = (float*)d_out;

    void *xh, *xl, *wh, *wl, *pwh, *pwl, *ah, *al;
    cudaGetSymbolAddress(&xh, g_xh);   cudaGetSymbolAddress(&xl, g_xl);
    cudaGetSymbolAddress(&wh, g_wh);   cudaGetSymbolAddress(&wl, g_wl);
    cudaGetSymbolAddress(&pwh, g_pwh); cudaGetSymbolAddress(&pwl, g_pwl);
    cudaGetSymbolAddress(&ah, g_ah);   cudaGetSymbolAddress(&al, g_al);

    const int gsmem = 2 * STAGE_B;                 // 131072
    cudaFuncSetAttribute(mma_gemm<0>, cudaFuncAttributeMaxDynamicSharedMemorySize, gsmem);
    cudaFuncSetAttribute(mma_gemm<1>, cudaFuncAttributeMaxDynamicSharedMemorySize, gsmem);
    const int asmem = 32768 + 2 * KVSTG;           // 98304
    cudaFuncSetAttribute(attn_mma, cudaFuncAttributeMaxDynamicSharedMemorySize, asmem);

    dim3 blk(256);
    split_bf16<<<(unsigned)(NX / 4 / 256), blk>>>(x, (__nv_bfloat16*)xh,
                                                  (__nv_bfloat16*)xl, NX);
    split_bf16<<<(unsigned)(NW / 4 / 256), blk>>>(qkv_w, (__nv_bfloat16*)wh,
                                                  (__nv_bfloat16*)wl, NW);
    split_bf16<<<(unsigned)(NPW / 4 / 256), blk>>>(proj_w, (__nv_bfloat16*)pwh,
                                                   (__nv_bfloat16*)pwl, NPW);
    // QKV GEMM -> bf16 hi/lo q/k/v (Q pre-scaled)
    mma_gemm<0><<<dim3(3 * DM / 128, MROWS / 128), blk, gsmem>>>(
        (const __nv_bfloat16*)xh, (const __nv_bfloat16*)xl,
        (const __nv_bfloat16*)wh, (const __nv_bfloat16*)wl,
        qkv_b, nullptr, 3 * DM);
    // flash attention -> bf16 hi/lo attn output
    attn_mma<<<dim3(SEQ / 128, NB * NH), blk, asmem>>>();
    // projection GEMM -> fp32 out
    mma_gemm<1><<<dim3(DM / 128, MROWS / 128), blk, gsmem>>>(
        (const __nv_bfloat16*)ah, (const __nv_bfloat16*)al,
        (const __nv_bfloat16*)pwh, (const __nv_bfloat16*)pwl,
        proj_b, out, DM);
}

// round 6
// speedup vs baseline: 4.0848x; 1.0749x over previous
#include <cuda_runtime.h>
#include <cuda_bf16.h>
#include <cstdint>

#define SEQ  2048
#define DM   1024
#define NH   16
#define HD   64
#define NB   2
#define MROWS (NB*SEQ)

// ---------------- scratch (device globals; no allocation allowed) ----------
#define NX   ((size_t)MROWS*DM)
#define NW   ((size_t)3*DM*DM)
#define NPW  ((size_t)DM*DM)
#define NQKV ((size_t)NB*NH*SEQ*HD)

__device__ __nv_bfloat16 g_xh[NX],  g_xl[NX];
__device__ __nv_bfloat16 g_wh[NW],  g_wl[NW];
__device__ __nv_bfloat16 g_pwh[NPW], g_pwl[NPW];
__device__ __nv_bfloat16 g_ah[NX],  g_al[NX];
__device__ __nv_bfloat16 g_qh[NQKV], g_ql[NQKV];
__device__ __nv_bfloat16 g_kh[NQKV], g_kl[NQKV];
__device__ __nv_bfloat16 g_vh[NQKV], g_vl[NQKV];

// ---------------- PTX helpers ----------------------------------------------
__device__ __forceinline__ uint32_t smem_u32(const void* p) {
    uint32_t a;
    asm("{ .reg .u64 t; cvta.to.shared.u64 t, %1; cvt.u32.u64 %0, t; }"
        : "=r"(a) : "l"(p));
    return a;
}
#define CP16(s, g) \
    asm volatile("cp.async.cg.shared.global [%0], [%1], 16;" :: "r"(s), "l"(g))
#define CP_COMMIT() asm volatile("cp.async.commit_group;" ::: "memory")
#define CP_WAIT1()  asm volatile("cp.async.wait_group 1;" ::: "memory")
#define CP_WAIT0()  asm volatile("cp.async.wait_group 0;" ::: "memory")

__device__ __forceinline__ uint32_t sw128(uint32_t off) {
    return off ^ ((off >> 3) & 0x70);
}
__device__ __forceinline__ void ldm_x4(uint32_t* r, uint32_t a) {
    asm volatile("ldmatrix.sync.aligned.m8n8.x4.shared.b16 {%0,%1,%2,%3}, [%4];"
        : "=r"(r[0]), "=r"(r[1]), "=r"(r[2]), "=r"(r[3]) : "r"(a));
}
__device__ __forceinline__ void ldm_x4t(uint32_t* r, uint32_t a) {
    asm volatile("ldmatrix.sync.aligned.m8n8.x4.trans.shared.b16 {%0,%1,%2,%3}, [%4];"
        : "=r"(r[0]), "=r"(r[1]), "=r"(r[2]), "=r"(r[3]) : "r"(a));
}
__device__ __forceinline__ void mma_bf16(float* c, const uint32_t* a,
                                         const uint32_t* b) {
    asm volatile(
        "mma.sync.aligned.m16n8k16.row.col.f32.bf16.bf16.f32 "
        "{%0,%1,%2,%3}, {%4,%5,%6,%7}, {%8,%9}, {%0,%1,%2,%3};"
        : "+f"(c[0]), "+f"(c[1]), "+f"(c[2]), "+f"(c[3])
        : "r"(a[0]), "r"(a[1]), "r"(a[2]), "r"(a[3]), "r"(b[0]), "r"(b[1]));
}
__device__ __forceinline__ uint32_t cvt2(float hi, float lo) {
    uint32_t r;
    asm("cvt.rn.bf16x2.f32 %0, %1, %2;" : "=r"(r) : "f"(hi), "f"(lo));
    return r;
}

// ---------------- fp32 -> bf16 hi/lo split ----------------------------------
__global__ void __launch_bounds__(256)
split_bf16(const float* __restrict__ in, __nv_bfloat16* __restrict__ hi,
           __nv_bfloat16* __restrict__ lo, size_t n)
{
    size_t i = ((size_t)blockIdx.x * 256 + threadIdx.x) * 4;
    if (i >= n) return;
    float4 v = *(const float4*)(in + i);
    float f[4] = {v.x, v.y, v.z, v.w};
    __nv_bfloat16 h4[4], l4[4];
#pragma unroll
    for (int j = 0; j < 4; j++) {
        h4[j] = __float2bfloat16(f[j]);
        l4[j] = __float2bfloat16(f[j] - __bfloat162float(h4[j]));
    }
    *(uint2*)(hi + i) = *(uint2*)h4;
    *(uint2*)(lo + i) = *(uint2*)l4;
}

// ---------------------------------------------------------------------------
// mma.sync bf16-split GEMM: C[M,N] = A[M,1024] @ W[N,1024]^T + bias
// CTA 128x256, 8 warps (2m x 4n), warp tile 64x64, BK=64 (SW128 smem),
// 2-stage cp.async. 3-term split.
// MODE 0: split + scatter into g_{q,k,v}{h,l} ([B,H,N,hd]), Q scaled 0.125
// MODE 1: row-major fp32 C
// ---------------------------------------------------------------------------
#define A_T 16384              // 128 x 64 bf16 tile
#define W_T 32768              // 256 x 64 bf16 tile
#define STAGE_B (2*A_T + 2*W_T)    // 98304

template<int MODE>
__global__ void __launch_bounds__(256)
mma_gemm(const __nv_bfloat16* __restrict__ Ah, const __nv_bfloat16* __restrict__ Al,
         const __nv_bfloat16* __restrict__ Wh, const __nv_bfloat16* __restrict__ Wl,
         const float* __restrict__ bias, float* __restrict__ C, int N)
{
    constexpr int K = 1024, KT = K / 64;
    extern __shared__ char dsm[];
    const uint32_t smb = smem_u32(dsm);

    const int tid = threadIdx.x, lane = tid & 31, wid = tid >> 5;
    const int wm = wid & 1, wn = wid >> 1;            // 2m x 4n
    const int bn = blockIdx.x * 256, bm = blockIdx.y * 128;

    const __nv_bfloat16* gA[2] = {Ah + (size_t)bm * K, Al + (size_t)bm * K};
    const __nv_bfloat16* gW[2] = {Wh + (size_t)bn * K, Wl + (size_t)bn * K};

    auto load_stage = [&](int s, int kt) {
        const uint32_t base = smb + s * STAGE_B;
#pragma unroll
        for (int h = 0; h < 2; h++) {                 // A hi/lo: 128 rows
            const uint32_t tb = base + h * A_T;
            const __nv_bfloat16* g = gA[h] + (size_t)kt * 64;
#pragma unroll
            for (int i = 0; i < 4; i++) {
                int idx = tid + i * 256;
                int r = idx >> 3, seg = idx & 7;
                CP16(tb + sw128(r * 128 + seg * 16), g + (size_t)r * K + seg * 8);
            }
        }
#pragma unroll
        for (int h = 0; h < 2; h++) {                 // W hi/lo: 256 rows
            const uint32_t tb = base + 2 * A_T + h * W_T;
            const __nv_bfloat16* g = gW[h] + (size_t)kt * 64;
#pragma unroll
            for (int i = 0; i < 8; i++) {
                int idx = tid + i * 256;
                int r = idx >> 3, seg = idx & 7;
                CP16(tb + sw128(r * 128 + seg * 16), g + (size_t)r * K + seg * 8);
            }
        }
        CP_COMMIT();
    };

    float acc[4][8][4];
#pragma unroll
    for (int mt = 0; mt < 4; mt++)
#pragma unroll
        for (int nt = 0; nt < 8; nt++)
#pragma unroll
            for (int j = 0; j < 4; j++) acc[mt][nt][j] = 0.f;

    const int a_row = wm * 64 + (lane & 15);
    const int a_kb  = (lane >> 4) * 16;
    const int b_row = wn * 64 + (lane & 7) + ((lane >> 4) << 3);
    const int b_kb  = ((lane >> 3) & 1) * 16;

    load_stage(0, 0);
    load_stage(1, 1);

    for (int t = 0; t < KT; t++) {
        const int s = t & 1;
        if (t == KT - 1) { CP_WAIT0(); } else { CP_WAIT1(); }
        __syncthreads();

        const uint32_t bAh = smb + s * STAGE_B;
        const uint32_t bAl = bAh + A_T;
        const uint32_t bWh = bAh + 2 * A_T;
        const uint32_t bWl = bWh + W_T;

#pragma unroll
        for (int ks = 0; ks < 4; ks++) {
            uint32_t afh[4][4], afl[4][4];
#pragma unroll
            for (int mt = 0; mt < 4; mt++) {
                const uint32_t off = sw128((a_row + mt * 16) * 128 + a_kb + ks * 32);
                ldm_x4(afh[mt], bAh + off);
                ldm_x4(afl[mt], bAl + off);
            }
#pragma unroll
            for (int ng = 0; ng < 4; ng++) {
                uint32_t bfh[4], bfl[4];
                const uint32_t off = sw128((b_row + ng * 16) * 128 + b_kb + ks * 32);
                ldm_x4(bfh, bWh + off);
                ldm_x4(bfl, bWl + off);
#pragma unroll
                for (int mt = 0; mt < 4; mt++) {
                    mma_bf16(acc[mt][2*ng],   afh[mt], &bfh[0]);
                    mma_bf16(acc[mt][2*ng],   afh[mt], &bfl[0]);
                    mma_bf16(acc[mt][2*ng],   afl[mt], &bfh[0]);
                    mma_bf16(acc[mt][2*ng+1], afh[mt], &bfh[2]);
                    mma_bf16(acc[mt][2*ng+1], afh[mt], &bfl[2]);
                    mma_bf16(acc[mt][2*ng+1], afl[mt], &bfh[2]);
                }
            }
        }
        __syncthreads();
        if (t + 2 < KT) load_stage(s, t + 2);
    }

    const int gr = lane >> 2, gc = (lane & 3) * 2;
#pragma unroll
    for (int mt = 0; mt < 4; mt++) {
#pragma unroll
        for (int half = 0; half < 2; half++) {
            const int m = bm + wm * 64 + mt * 16 + gr + half * 8;
#pragma unroll
            for (int nt = 0; nt < 8; nt++) {
                const int n = bn + wn * 64 + nt * 8 + gc;
                float vx = acc[mt][nt][half * 2 + 0] + __ldg(bias + n);
                float vy = acc[mt][nt][half * 2 + 1] + __ldg(bias + n + 1);
                if (MODE == 0) {
                    const int chunk = n >> 10, rem = n & 1023;
                    const int h = rem >> 6, d = rem & 63;
                    const int b = m >> 11, tt = m & 2047;
                    if (chunk == 0) { vx *= 0.125f; vy *= 0.125f; }
                    __nv_bfloat16 hx = __float2bfloat16(vx);
                    __nv_bfloat16 hy = __float2bfloat16(vy);
                    __nv_bfloat16 lx = __float2bfloat16(vx - __bfloat162float(hx));
                    __nv_bfloat16 ly = __float2bfloat16(vy - __bfloat162float(hy));
                    __nv_bfloat16* dh = (chunk == 0) ? g_qh : (chunk == 1) ? g_kh : g_vh;
                    __nv_bfloat16* dl = (chunk == 0) ? g_ql : (chunk == 1) ? g_kl : g_vl;
                    const size_t off = (((size_t)b * NH + h) * SEQ + tt) * HD + d;
                    __nv_bfloat162 ph; ph.x = hx; ph.y = hy;
                    __nv_bfloat162 pl; pl.x = lx; pl.y = ly;
                    *(__nv_bfloat162*)&dh[off] = ph;
                    *(__nv_bfloat162*)&dl[off] = pl;
                } else {
                    float2 v; v.x = vx; v.y = vy;
                    *(float2*)&C[(size_t)m * N + n] = v;
                }
            }
        }
    }
}

// ---------------------------------------------------------------------------
// mma.sync flash attention, bf16 3-term split, register-resident P.
// CTA: 128 queries x one (b,h); 4 warps x 32 q-rows (warp tile 32x64);
// 64-key tiles, double-buffered cp.async. smem 96 KB -> 2 CTAs/SM.
// ---------------------------------------------------------------------------
#define KVSTG 32768

__global__ void __launch_bounds__(128) attn_mma()
{
    extern __shared__ char axm[];
    const uint32_t smb = smem_u32(axm);
    const int tid = threadIdx.x, lane = tid & 31, wid = tid >> 5;
    const int bh = blockIdx.y, q0 = blockIdx.x * 128;
    const int wq = wid * 32;

    const size_t gbase = (size_t)bh * SEQ * HD;
    const __nv_bfloat16* pQh = g_qh + gbase + (size_t)q0 * HD;
    const __nv_bfloat16* pQl = g_ql + gbase + (size_t)q0 * HD;

    // Q tiles (hi/lo), 128 rows x 128B, SW128
#pragma unroll
    for (int i = 0; i < 8; i++) {
        int idx = tid + i * 128;
        int r = idx >> 3, seg = idx & 7;
        const uint32_t so = sw128(r * 128 + seg * 16);
        CP16(smb + so,         pQh + (size_t)r * HD + seg * 8);
        CP16(smb + 16384 + so, pQl + (size_t)r * HD + seg * 8);
    }

    const __nv_bfloat16* gkv[4] = {g_kh + gbase, g_kl + gbase,
                                   g_vh + gbase, g_vl + gbase};
    auto load_kv = [&](int s, int it) {
        const uint32_t base = smb + 32768 + s * KVSTG;
#pragma unroll
        for (int sel = 0; sel < 4; sel++) {
            const __nv_bfloat16* g = gkv[sel] + (size_t)it * 64 * HD;
#pragma unroll
            for (int i = 0; i < 4; i++) {
                int idx = tid + i * 128;
                int r = idx >> 3, seg = idx & 7;
                CP16(base + sel * 8192 + sw128(r * 128 + seg * 16),
                     g + (size_t)r * HD + seg * 8);
            }
        }
        CP_COMMIT();
    };
    load_kv(0, 0);   // group 0 also covers the Q loads above
    load_kv(1, 1);

    const int a_row = wq + (lane & 15);
    const int a_kb  = (lane >> 4) * 16;
    const int b_row = (lane & 7) + ((lane >> 4) << 3);
    const int b_kb  = ((lane >> 3) & 1) * 16;
    const int v_row = (lane & 7) + (((lane >> 3) & 1) << 3);
    const int v_cb  = (lane >> 4) * 16;

    float sO[2][8][4];
#pragma unroll
    for (int mt = 0; mt < 2; mt++)
#pragma unroll
        for (int nt = 0; nt < 8; nt++)
#pragma unroll
            for (int j = 0; j < 4; j++) sO[mt][nt][j] = 0.f;
    float m_i[4] = {-1e30f, -1e30f, -1e30f, -1e30f};
    float l_i[4] = {0.f, 0.f, 0.f, 0.f};

    for (int it = 0; it < SEQ / 64; it++) {
        const int s = it & 1;
        if (it == SEQ / 64 - 1) { CP_WAIT0(); } else { CP_WAIT1(); }
        __syncthreads();

        const uint32_t bKh = smb + 32768 + s * KVSTG;
        const uint32_t bKl = bKh + 8192;
        const uint32_t bVh = bKh + 16384;
        const uint32_t bVl = bKh + 24576;

        // ---- S = Q K^T (32 q x 64 keys per warp) ----
        float sS[2][8][4];
#pragma unroll
        for (int mt = 0; mt < 2; mt++)
#pragma unroll
            for (int nt = 0; nt < 8; nt++)
#pragma unroll
                for (int j = 0; j < 4; j++) sS[mt][nt][j] = 0.f;

#pragma unroll
        for (int ks = 0; ks < 4; ks++) {
            uint32_t qh[2][4], ql[2][4];
#pragma unroll
            for (int mt = 0; mt < 2; mt++) {
                const uint32_t aoff = sw128((a_row + mt * 16) * 128 + a_kb + ks * 32);
                ldm_x4(qh[mt], smb + aoff);
                ldm_x4(ql[mt], smb + 16384 + aoff);
            }
#pragma unroll
            for (int ng = 0; ng < 4; ng++) {
                uint32_t kh[4], kl[4];
                const uint32_t off = sw128((ng * 16 + b_row) * 128 + b_kb + ks * 32);
                ldm_x4(kh, bKh + off);
                ldm_x4(kl, bKl + off);
#pragma unroll
                for (int mt = 0; mt < 2; mt++) {
                    mma_bf16(sS[mt][2*ng],   qh[mt], &kh[0]);
                    mma_bf16(sS[mt][2*ng],   qh[mt], &kl[0]);
                    mma_bf16(sS[mt][2*ng],   ql[mt], &kh[0]);
                    mma_bf16(sS[mt][2*ng+1], qh[mt], &kh[2]);
                    mma_bf16(sS[mt][2*ng+1], qh[mt], &kl[2]);
                    mma_bf16(sS[mt][2*ng+1], ql[mt], &kh[2]);
                }
            }
        }

        // ---- online softmax (4 row-groups: mt*2 + half) ----
#pragma unroll
        for (int mt = 0; mt < 2; mt++) {
            float mx0 = -1e30f, mx1 = -1e30f;
#pragma unroll
            for (int nt = 0; nt < 8; nt++) {
                mx0 = fmaxf(mx0, fmaxf(sS[mt][nt][0], sS[mt][nt][1]));
                mx1 = fmaxf(mx1, fmaxf(sS[mt][nt][2], sS[mt][nt][3]));
            }
            mx0 = fmaxf(mx0, __shfl_xor_sync(0xffffffffu, mx0, 1));
            mx0 = fmaxf(mx0, __shfl_xor_sync(0xffffffffu, mx0, 2));
            mx1 = fmaxf(mx1, __shfl_xor_sync(0xffffffffu, mx1, 1));
            mx1 = fmaxf(mx1, __shfl_xor_sync(0xffffffffu, mx1, 2));
            const float mn0 = fmaxf(m_i[mt*2],   mx0);
            const float mn1 = fmaxf(m_i[mt*2+1], mx1);
            const float al0 = __expf(m_i[mt*2]   - mn0);
            const float al1 = __expf(m_i[mt*2+1] - mn1);
            float rs0 = 0.f, rs1 = 0.f;
#pragma unroll
            for (int nt = 0; nt < 8; nt++) {
                sS[mt][nt][0] = __expf(sS[mt][nt][0] - mn0);
                sS[mt][nt][1] = __expf(sS[mt][nt][1] - mn0);
                sS[mt][nt][2] = __expf(sS[mt][nt][2] - mn1);
                sS[mt][nt][3] = __expf(sS[mt][nt][3] - mn1);
                rs0 += sS[mt][nt][0] + sS[mt][nt][1];
                rs1 += sS[mt][nt][2] + sS[mt][nt][3];
            }
            rs0 += __shfl_xor_sync(0xffffffffu, rs0, 1);
            rs0 += __shfl_xor_sync(0xffffffffu, rs0, 2);
            rs1 += __shfl_xor_sync(0xffffffffu, rs1, 1);
            rs1 += __shfl_xor_sync(0xffffffffu, rs1, 2);
            l_i[mt*2]   = l_i[mt*2]   * al0 + rs0;  m_i[mt*2]   = mn0;
            l_i[mt*2+1] = l_i[mt*2+1] * al1 + rs1;  m_i[mt*2+1] = mn1;
#pragma unroll
            for (int nt = 0; nt < 8; nt++) {
                sO[mt][nt][0] *= al0; sO[mt][nt][1] *= al0;
                sO[mt][nt][2] *= al1; sO[mt][nt][3] *= al1;
            }
        }

        // ---- O += P V (P register-resident, split hi/lo) ----
#pragma unroll
        for (int ks = 0; ks < 4; ks++) {
            uint32_t ph[2][4], pl[2][4];
#pragma unroll
            for (int mt = 0; mt < 2; mt++) {
                const float* t0 = sS[mt][2 * ks];
                const float* t1 = sS[mt][2 * ks + 1];
                const float src[8] = {t0[0], t0[1], t0[2], t0[3],
                                      t1[0], t1[1], t1[2], t1[3]};
#pragma unroll
                for (int j = 0; j < 4; j++) {
                    const float p0 = src[j * 2], p1 = src[j * 2 + 1];
                    const uint32_t hp = cvt2(p1, p0);
                    ph[mt][j] = hp;
                    const float f0 = __uint_as_float(hp << 16);
                    const float f1 = __uint_as_float(hp & 0xffff0000u);
                    pl[mt][j] = cvt2(p1 - f1, p0 - f0);
                }
            }
#pragma unroll
            for (int dg = 0; dg < 4; dg++) {
                uint32_t vh[4], vl[4];
                const uint32_t off = sw128((ks * 16 + v_row) * 128 + dg * 32 + v_cb);
                ldm_x4t(vh, bVh + off);
                ldm_x4t(vl, bVl + off);
#pragma unroll
                for (int mt = 0; mt < 2; mt++) {
                    mma_bf16(sO[mt][2*dg],   ph[mt], &vh[0]);
                    mma_bf16(sO[mt][2*dg],   ph[mt], &vl[0]);
                    mma_bf16(sO[mt][2*dg],   pl[mt], &vh[0]);
                    mma_bf16(sO[mt][2*dg+1], ph[mt], &vh[2]);
                    mma_bf16(sO[mt][2*dg+1], ph[mt], &vl[2]);
                    mma_bf16(sO[mt][2*dg+1], pl[mt], &vh[2]);
                }
            }
        }

        __syncthreads();
        if (it + 2 < SEQ / 64) load_kv(s, it + 2);
    }

    // ---- epilogue: O/l -> bf16 hi/lo into g_ah/g_al ([B,N,H*hd]) ----
    const int b = bh >> 4, h = bh & 15;
    const int dc = (lane & 3) * 2;
#pragma unroll
    for (int mt = 0; mt < 2; mt++) {
        const float inv0 = 1.f / l_i[mt*2], inv1 = 1.f / l_i[mt*2+1];
        const int qr = q0 + wq + mt * 16 + (lane >> 2);
        const size_t base0 = ((size_t)b * SEQ + qr) * DM + h * HD + dc;
        const size_t base1 = base0 + (size_t)8 * DM;
#pragma unroll
        for (int nt = 0; nt < 8; nt++) {
            const float v0 = sO[mt][nt][0] * inv0, v1 = sO[mt][nt][1] * inv0;
            const float v2 = sO[mt][nt][2] * inv1, v3 = sO[mt][nt][3] * inv1;
            uint32_t h01 = cvt2(v1, v0);
            uint32_t l01 = cvt2(v1 - __uint_as_float(h01 & 0xffff0000u),
                                v0 - __uint_as_float(h01 << 16));
            uint32_t h23 = cvt2(v3, v2);
            uint32_t l23 = cvt2(v3 - __uint_as_float(h23 & 0xffff0000u),
                                v2 - __uint_as_float(h23 << 16));
            *(uint32_t*)&g_ah[base0 + nt * 8] = h01;
            *(uint32_t*)&g_al[base0 + nt * 8] = l01;
            *(uint32_t*)&g_ah[base1 + nt * 8] = h23;
            *(uint32_t*)&g_al[base1 + nt * 8] = l23;
        }
    }
}

// ---------------------------------------------------------------------------
extern "C" void kernel_launch(void* const* d_in, const int* in_sizes, int n_in,
                              void* d_out, int out_size)
{
    const float* x      = (const float*)d_in[0];
    const float* qkv_w  = (const float*)d_in[1];
    const float* qkv_b  = (const float*)d_in[2];
    const float* proj_w = (const float*)d_in[3];
    const float* proj_b = (const float*)d_in[4];
    float* out = (float*)d_out;

    void *xh, *xl, *wh, *wl, *pwh, *pwl, *ah, *al;
    cudaGetSymbolAddress(&xh, g_xh);   cudaGetSymbolAddress(&xl, g_xl);
    cudaGetSymbolAddress(&wh, g_wh);   cudaGetSymbolAddress(&wl, g_wl);
    cudaGetSymbolAddress(&pwh, g_pwh); cudaGetSymbolAddress(&pwl, g_pwl);
    cudaGetSymbolAddress(&ah, g_ah);   cudaGetSymbolAddress(&al, g_al);

    const int gsmem = 2 * STAGE_B;                 // 196608
    cudaFuncSetAttribute(mma_gemm<0>, cudaFuncAttributeMaxDynamicSharedMemorySize, gsmem);
    cudaFuncSetAttribute(mma_gemm<1>, cudaFuncAttributeMaxDynamicSharedMemorySize, gsmem);
    const int asmem = 32768 + 2 * KVSTG;           // 98304
    cudaFuncSetAttribute(attn_mma, cudaFuncAttributeMaxDynamicSharedMemorySize, asmem);

    dim3 blk(256);
    split_bf16<<<(unsigned)(NX / 4 / 256), blk>>>(x, (__nv_bfloat16*)xh,
                                                  (__nv_bfloat16*)xl, NX);
    split_bf16<<<(unsigned)(NW / 4 / 256), blk>>>(qkv_w, (__nv_bfloat16*)wh,
                                                  (__nv_bfloat16*)wl, NW);
    split_bf16<<<(unsigned)(NPW / 4 / 256), blk>>>(proj_w, (__nv_bfloat16*)pwh,
                                                   (__nv_bfloat16*)pwl, NPW);
    // QKV GEMM -> bf16 hi/lo q/k/v (Q pre-scaled)
    mma_gemm<0><<<dim3(3 * DM / 256, MROWS / 128), blk, gsmem>>>(
        (const __nv_bfloat16*)xh, (const __nv_bfloat16*)xl,
        (const __nv_bfloat16*)wh, (const __nv_bfloat16*)wl,
        qkv_b, nullptr, 3 * DM);
    // flash attention -> bf16 hi/lo attn output
    attn_mma<<<dim3(SEQ / 128, NB * NH), dim3(128), asmem>>>();
    // projection GEMM -> fp32 out
    mma_gemm<1><<<dim3(DM / 256, MROWS / 128), blk, gsmem>>>(
        (const __nv_bfloat16*)ah, (const __nv_bfloat16*)al,
        (const __nv_bfloat16*)pwh, (const __nv_bfloat16*)pwl,
        proj_b, out, DM);
}